// round 12
// baseline (speedup 1.0000x reference)
#include <cuda_runtime.h>
#include <cuda_bf16.h>

// BodyKinematics tree FK. B=4096, N=256, E=255.
// Round 12 (= R11 resubmit after infra failure): R5 logic per 256-thread
// half, 512-thread CTAs processing two batches side by side: 7 shared full
// barriers (was 16 per 2 batches), node 255 finished under a __syncwarp
// (producer+consumers in one warp), per-edge register state unchanged.

#define NN 256
#define EE 255
#define PI_F 3.14159265358979f

__device__ float4 g_tip[3 * EE];   // [row][edge] planes, lane-coalesced reads

__global__ void pack_kernel(const float* __restrict__ tip) {
    const int j = blockIdx.x * blockDim.x + threadIdx.x;   // float4 index in (E,4,4)
    if (j < EE * 4) {
        const int e = j >> 2, row = j & 3;
        const float4 v = ((const float4*)tip)[j];
        if (row < 3) g_tip[row * EE + e] = v;
    }
}

__device__ __forceinline__ float ftanh(float x) {
    float ax = fabsf(x);
    float t = __expf(2.0f * ax);
    float r = __fdividef(t - 1.0f, t + 1.0f);
    r = ax > 40.0f ? 1.0f : r;
    return copysignf(r, x);
}

// world_row = P.x*L0 + P.y*L1 + P.z*L2 (+ P.w in translation slot)
__device__ __forceinline__ float4 aff(float4 P, float4 L0, float4 L1, float4 L2) {
    float4 w;
    w.x = fmaf(P.x, L0.x, fmaf(P.y, L1.x, P.z * L2.x));
    w.y = fmaf(P.x, L0.y, fmaf(P.y, L1.y, P.z * L2.y));
    w.z = fmaf(P.x, L0.z, fmaf(P.y, L1.z, P.z * L2.z));
    w.w = fmaf(P.x, L0.w, fmaf(P.y, L1.w, fmaf(P.z, L2.w, P.w)));
    return w;
}

__global__ __launch_bounds__(512) void fk_kernel(
    const float* __restrict__ la,    // (B, 3E)
    float* __restrict__ out)         // (B, N, 4, 4)
{
    // Two independent world arrays (one per batch half), stride-3 float4
    // granules -> conflict-free LDS.128/STS.128. 24 KB total.
    __shared__ float4 S[2][NN * 3];

    const int tid = threadIdx.x;
    const int h = tid >> 8;          // half: 0 or 1
    const int u = tid & 255;         // local thread id within half
    const int b = 2 * blockIdx.x + h;
    float4* __restrict__ Sh = S[h];

    float4 L0, L1, L2;   // local affine rows for node u+1 (edge u)

    if (u < EE) {
        const float* lap = la + (size_t)b * (3 * EE) + 3 * u;
        const float tha = PI_F * ftanh(lap[0]);
        const float thb = PI_F * ftanh(lap[1]);
        const float thc = PI_F * ftanh(lap[2]);

        float sa, ca, sb, cb, sc, cc;
        __sincosf(tha, &sa, &ca);
        __sincosf(thb, &sb, &cb);
        __sincosf(thc, &sc, &cc);

        // M = Rx(a) * Ry(b) * Rz(c)
        float M[9];
        M[0] = cb * cc;
        M[1] = -cb * sc;
        M[2] = sb;
        M[3] = fmaf(sa * sb, cc, ca * sc);
        M[4] = fmaf(-sa * sb, sc, ca * cc);
        M[5] = -sa * cb;
        M[6] = fmaf(-ca * sb, cc, sa * sc);
        M[7] = fmaf(ca * sb, sc, sa * cc);
        M[8] = ca * cb;

        const float4 T0 = g_tip[u];
        const float4 T1 = g_tip[EE + u];
        const float4 T2 = g_tip[2 * EE + u];
        #define MT(r, D)                                                        \
            D.x = fmaf(M[3*r], T0.x, fmaf(M[3*r+1], T1.x, M[3*r+2] * T2.x));    \
            D.y = fmaf(M[3*r], T0.y, fmaf(M[3*r+1], T1.y, M[3*r+2] * T2.y));    \
            D.z = fmaf(M[3*r], T0.z, fmaf(M[3*r+1], T1.z, M[3*r+2] * T2.z));    \
            D.w = fmaf(M[3*r], T0.w, fmaf(M[3*r+1], T1.w, M[3*r+2] * T2.w));
        MT(0, L0) MT(1, L1) MT(2, L2)
        #undef MT
    } else {
        // u == 255: root identity for this half.
        Sh[0] = make_float4(1.f, 0.f, 0.f, 0.f);
        Sh[1] = make_float4(0.f, 1.f, 0.f, 0.f);
        Sh[2] = make_float4(0.f, 0.f, 1.f, 0.f);
    }
    __syncthreads();

    // Tree levels lo = 1,3,7,15,31,63,127 (node n = u+1). 7 full barriers.
    const int n = u + 1;   // u==255 -> n=256, never active
    #pragma unroll
    for (int lo = 1; lo < 128; lo = 2 * lo + 1) {
        const int hi = 2 * lo + 1;   // <=255
        if (n >= lo && n < hi) {
            const int p = (n - 1) >> 1;
            const float4 P0 = Sh[3 * p], P1 = Sh[3 * p + 1], P2 = Sh[3 * p + 2];
            Sh[3 * n]     = aff(P0, L0, L1, L2);
            Sh[3 * n + 1] = aff(P1, L0, L1, L2);
            Sh[3 * n + 2] = aff(P2, L0, L1, L2);
        }
        __syncthreads();
    }

    // Node 255 (n==255, u==254): parent 127 is final after the last barrier.
    // Its S rows are read only by output threads u=252..254 — same warp as
    // the producer, so a warp sync suffices.
    if (n == EE) {
        const float4 P0 = Sh[3 * 127], P1 = Sh[3 * 127 + 1], P2 = Sh[3 * 127 + 2];
        Sh[3 * EE]     = aff(P0, L0, L1, L2);
        Sh[3 * EE + 1] = aff(P1, L0, L1, L2);
        Sh[3 * EE + 2] = aff(P2, L0, L1, L2);
    }
    __syncwarp();

    // Coalesced output: each half writes its 16KB block in 4 contiguous rounds.
    float4* o = (float4*)(out + (size_t)b * NN * 16);
    const float4 r3 = make_float4(0.f, 0.f, 0.f, 1.f);
    #pragma unroll
    for (int k = 0; k < 4; ++k) {
        const int j = k * NN + u;
        const int node = j >> 2, row = j & 3;
        o[j] = (row < 3) ? Sh[3 * node + row] : r3;
    }
}

extern "C" void kernel_launch(void* const* d_in, const int* in_sizes, int n_in,
                              void* d_out, int out_size) {
    const float* la  = (const float*)d_in[0];
    const float* tip = (const float*)d_in[1];
    float* out = (float*)d_out;

    const int B = in_sizes[0] / (3 * EE);
    pack_kernel<<<4, 256>>>(tip);
    fk_kernel<<<B / 2, 512>>>(la, out);
}

// round 14
// speedup vs baseline: 1.0013x; 1.0013x over previous
#include <cuda_runtime.h>
#include <cuda_bf16.h>

// BodyKinematics tree FK. B=4096, N=256, E=255.
// Round 14 (= R13 resubmit after transient infra failure): R5 fk body
// VERBATIM. Pack prepass folded into CTA 0 with a release/acquire flag
// handshake (spin happens BEFORE the body, so no register liveness crosses a
// wait). Last CTA resets flag/counter so every graph replay starts clean.

#define NN 256
#define EE 255
#define PI_F 3.14159265358979f

__device__ float4 g_tip[3 * EE];   // [row][edge] planes, lane-coalesced reads
__device__ int g_flag = 0;         // set by CTA 0 when g_tip is ready
__device__ int g_done = 0;         // CTA completion counter (for reset)

__device__ __forceinline__ float ftanh(float x) {
    float ax = fabsf(x);
    float t = __expf(2.0f * ax);
    float r = __fdividef(t - 1.0f, t + 1.0f);
    r = ax > 40.0f ? 1.0f : r;
    return copysignf(r, x);
}

// world_row = P.x*L0 + P.y*L1 + P.z*L2 (+ P.w in translation slot)
__device__ __forceinline__ float4 aff(float4 P, float4 L0, float4 L1, float4 L2) {
    float4 w;
    w.x = fmaf(P.x, L0.x, fmaf(P.y, L1.x, P.z * L2.x));
    w.y = fmaf(P.x, L0.y, fmaf(P.y, L1.y, P.z * L2.y));
    w.z = fmaf(P.x, L0.z, fmaf(P.y, L1.z, P.z * L2.z));
    w.w = fmaf(P.x, L0.w, fmaf(P.y, L1.w, fmaf(P.z, L2.w, P.w)));
    return w;
}

__global__ __launch_bounds__(256) void fk_kernel(
    const float* __restrict__ la,    // (B, 3E)
    const float* __restrict__ tip,   // (E,4,4)
    float* __restrict__ out)         // (B, N, 4, 4)
{
    // World affines: S[node*3 + row]. Stride-3 float4 granules (48 B/node,
    // coprime with banks) -> conflict-free LDS.128/STS.128. 12 KB.
    __shared__ float4 S[NN * 3];

    const int b = blockIdx.x;
    const int t = threadIdx.x;

    // ---- g_tip handshake (replaces the separate pack kernel) ----
    if (b == 0) {
        // CTA 0 deinterleaves tip into g_tip planes (coalesced).
        const float4* tp4 = (const float4*)tip;
        #pragma unroll
        for (int k = 0; k < 4; ++k) {
            const int j = k * NN + t;
            if (j < EE * 4) {
                const float4 v = __ldg(tp4 + j);
                const int row = j & 3;
                if (row < 3) g_tip[row * EE + (j >> 2)] = v;
            }
        }
        __syncthreads();                       // CTA-0 stores done + visible in-block
        if (t == 0) {
            __threadfence();                   // publish g_tip GPU-wide
            asm volatile("st.release.gpu.global.b32 [%0], %1;"
                         :: "l"(&g_flag), "r"(1) : "memory");
        }
    } else {
        if (t == 0) {
            int f;
            while (true) {
                asm volatile("ld.acquire.gpu.global.b32 %0, [%1];"
                             : "=r"(f) : "l"(&g_flag) : "memory");
                if (f) break;
                __nanosleep(64);
            }
        }
        __syncthreads();                       // broadcast readiness to the CTA
    }

    // ================= R5 body (verbatim) =================
    float4 L0, L1, L2;   // local affine rows for node t+1 (edge t)

    if (t < EE) {
        const float* lap = la + (size_t)b * (3 * EE) + 3 * t;
        const float tha = PI_F * ftanh(lap[0]);
        const float thb = PI_F * ftanh(lap[1]);
        const float thc = PI_F * ftanh(lap[2]);

        float sa, ca, sb, cb, sc, cc;
        __sincosf(tha, &sa, &ca);
        __sincosf(thb, &sb, &cb);
        __sincosf(thc, &sc, &cc);

        // M = Rx(a) * Ry(b) * Rz(c)
        float M[9];
        M[0] = cb * cc;
        M[1] = -cb * sc;
        M[2] = sb;
        M[3] = fmaf(sa * sb, cc, ca * sc);
        M[4] = fmaf(-sa * sb, sc, ca * cc);
        M[5] = -sa * cb;
        M[6] = fmaf(-ca * sb, cc, sa * sc);
        M[7] = fmaf(ca * sb, sc, sa * cc);
        M[8] = ca * cb;

        const float4 T0 = g_tip[t];
        const float4 T1 = g_tip[EE + t];
        const float4 T2 = g_tip[2 * EE + t];
        #define MT(r, D)                                                        \
            D.x = fmaf(M[3*r], T0.x, fmaf(M[3*r+1], T1.x, M[3*r+2] * T2.x));    \
            D.y = fmaf(M[3*r], T0.y, fmaf(M[3*r+1], T1.y, M[3*r+2] * T2.y));    \
            D.z = fmaf(M[3*r], T0.z, fmaf(M[3*r+1], T1.z, M[3*r+2] * T2.z));    \
            D.w = fmaf(M[3*r], T0.w, fmaf(M[3*r+1], T1.w, M[3*r+2] * T2.w));
        MT(0, L0) MT(1, L1) MT(2, L2)
        #undef MT
    } else {
        // Root: identity world.
        S[0] = make_float4(1.f, 0.f, 0.f, 0.f);
        S[1] = make_float4(0.f, 1.f, 0.f, 0.f);
        S[2] = make_float4(0.f, 0.f, 1.f, 0.f);
    }
    __syncthreads();

    // Level-parallel tree on node n = t+1: levels lo = 1,3,7,15,31,63,127,255.
    const int n = t + 1;   // thread 255 -> n=256, never active below
    #pragma unroll
    for (int lo = 1; lo < NN; lo = 2 * lo + 1) {
        const int hi = (2 * lo + 1 < NN) ? (2 * lo + 1) : NN;
        if (n >= lo && n < hi) {
            const int p = (n - 1) >> 1;
            const float4 P0 = S[3 * p], P1 = S[3 * p + 1], P2 = S[3 * p + 2];
            S[3 * n]     = aff(P0, L0, L1, L2);
            S[3 * n + 1] = aff(P1, L0, L1, L2);
            S[3 * n + 2] = aff(P2, L0, L1, L2);
        }
        __syncthreads();
    }

    // Coalesced output: CTA writes its 16KB block in 4 contiguous rounds.
    float4* o = (float4*)(out + (size_t)b * NN * 16);
    const float4 r3 = make_float4(0.f, 0.f, 0.f, 1.f);
    #pragma unroll
    for (int k = 0; k < 4; ++k) {
        const int j = k * NN + t;
        const int node = j >> 2, row = j & 3;
        o[j] = (row < 3) ? S[3 * node + row] : r3;
    }
    // ================= end R5 body =================

    // Reset handshake state for the next graph replay. Every CTA's flag read
    // precedes its increment, so the reset (by the last CTA) cannot race a
    // spinning CTA. Leaves g_flag = g_done = 0 for the next launch.
    if (t == 0) {
        const int d = atomicAdd(&g_done, 1);
        if (d == (int)gridDim.x - 1) {
            g_done = 0;
            asm volatile("st.release.gpu.global.b32 [%0], %1;"
                         :: "l"(&g_flag), "r"(0) : "memory");
        }
    }
}

extern "C" void kernel_launch(void* const* d_in, const int* in_sizes, int n_in,
                              void* d_out, int out_size) {
    const float* la  = (const float*)d_in[0];
    const float* tip = (const float*)d_in[1];
    float* out = (float*)d_out;

    const int B = in_sizes[0] / (3 * EE);
    fk_kernel<<<B, NN>>>(la, tip, out);
}

// round 15
// speedup vs baseline: 1.1715x; 1.1700x over previous
#include <cuda_runtime.h>
#include <cuda_bf16.h>

// BodyKinematics tree FK. B=4096, N=256, E=255.
// Round 15: R5 VERBATIM (pack prepass + g_tip planes + lean fk), with ONE
// change: fk is PDL-launched and executes cudaGridDependencySynchronize() as
// its FIRST statement (zero register liveness across the wait, unlike R10).
// This overlaps fk's launch ramp with pack's execution.

#define NN 256
#define EE 255
#define PI_F 3.14159265358979f

__device__ float4 g_tip[3 * EE];   // [row][edge] planes, lane-coalesced reads

__global__ void pack_kernel(const float* __restrict__ tip) {
    const int j = blockIdx.x * blockDim.x + threadIdx.x;   // float4 index in (E,4,4)
    if (j < EE * 4) {
        const int e = j >> 2, row = j & 3;
        const float4 v = ((const float4*)tip)[j];
        if (row < 3) g_tip[row * EE + e] = v;
    }
    // Release the dependent fk grid as early as possible.
    cudaTriggerProgrammaticLaunchCompletion();
}

__device__ __forceinline__ float ftanh(float x) {
    float ax = fabsf(x);
    float t = __expf(2.0f * ax);
    float r = __fdividef(t - 1.0f, t + 1.0f);
    r = ax > 40.0f ? 1.0f : r;
    return copysignf(r, x);
}

// world_row = P.x*L0 + P.y*L1 + P.z*L2 (+ P.w in translation slot)
__device__ __forceinline__ float4 aff(float4 P, float4 L0, float4 L1, float4 L2) {
    float4 w;
    w.x = fmaf(P.x, L0.x, fmaf(P.y, L1.x, P.z * L2.x));
    w.y = fmaf(P.x, L0.y, fmaf(P.y, L1.y, P.z * L2.y));
    w.z = fmaf(P.x, L0.z, fmaf(P.y, L1.z, P.z * L2.z));
    w.w = fmaf(P.x, L0.w, fmaf(P.y, L1.w, fmaf(P.z, L2.w, P.w)));
    return w;
}

__global__ __launch_bounds__(256) void fk_kernel(
    const float* __restrict__ la,    // (B, 3E)
    float* __restrict__ out)         // (B, N, 4, 4)
{
    // FIRST: wait for pack_kernel's g_tip writes. Nothing is live here, so
    // this costs no registers — it only gates instruction issue.
    cudaGridDependencySynchronize();

    // World affines: S[node*3 + row]. Stride-3 float4 granules (48 B/node,
    // coprime with banks) -> conflict-free LDS.128/STS.128. 12 KB.
    __shared__ float4 S[NN * 3];

    const int b = blockIdx.x;
    const int t = threadIdx.x;

    float4 L0, L1, L2;   // local affine rows for node t+1 (edge t)

    if (t < EE) {
        const float* lap = la + (size_t)b * (3 * EE) + 3 * t;
        const float tha = PI_F * ftanh(lap[0]);
        const float thb = PI_F * ftanh(lap[1]);
        const float thc = PI_F * ftanh(lap[2]);

        float sa, ca, sb, cb, sc, cc;
        __sincosf(tha, &sa, &ca);
        __sincosf(thb, &sb, &cb);
        __sincosf(thc, &sc, &cc);

        // M = Rx(a) * Ry(b) * Rz(c)
        float M[9];
        M[0] = cb * cc;
        M[1] = -cb * sc;
        M[2] = sb;
        M[3] = fmaf(sa * sb, cc, ca * sc);
        M[4] = fmaf(-sa * sb, sc, ca * cc);
        M[5] = -sa * cb;
        M[6] = fmaf(-ca * sb, cc, sa * sc);
        M[7] = fmaf(ca * sb, sc, sa * cc);
        M[8] = ca * cb;

        const float4 T0 = g_tip[t];
        const float4 T1 = g_tip[EE + t];
        const float4 T2 = g_tip[2 * EE + t];
        #define MT(r, D)                                                        \
            D.x = fmaf(M[3*r], T0.x, fmaf(M[3*r+1], T1.x, M[3*r+2] * T2.x));    \
            D.y = fmaf(M[3*r], T0.y, fmaf(M[3*r+1], T1.y, M[3*r+2] * T2.y));    \
            D.z = fmaf(M[3*r], T0.z, fmaf(M[3*r+1], T1.z, M[3*r+2] * T2.z));    \
            D.w = fmaf(M[3*r], T0.w, fmaf(M[3*r+1], T1.w, M[3*r+2] * T2.w));
        MT(0, L0) MT(1, L1) MT(2, L2)
        #undef MT
    } else {
        // Root: identity world.
        S[0] = make_float4(1.f, 0.f, 0.f, 0.f);
        S[1] = make_float4(0.f, 1.f, 0.f, 0.f);
        S[2] = make_float4(0.f, 0.f, 1.f, 0.f);
    }
    __syncthreads();

    // Level-parallel tree on node n = t+1: levels lo = 1,3,7,15,31,63,127,255.
    const int n = t + 1;   // thread 255 -> n=256, never active below
    #pragma unroll
    for (int lo = 1; lo < NN; lo = 2 * lo + 1) {
        const int hi = (2 * lo + 1 < NN) ? (2 * lo + 1) : NN;
        if (n >= lo && n < hi) {
            const int p = (n - 1) >> 1;
            const float4 P0 = S[3 * p], P1 = S[3 * p + 1], P2 = S[3 * p + 2];
            S[3 * n]     = aff(P0, L0, L1, L2);
            S[3 * n + 1] = aff(P1, L0, L1, L2);
            S[3 * n + 2] = aff(P2, L0, L1, L2);
        }
        __syncthreads();
    }

    // Coalesced output: CTA writes its 16KB block in 4 contiguous rounds.
    float4* o = (float4*)(out + (size_t)b * NN * 16);
    const float4 r3 = make_float4(0.f, 0.f, 0.f, 1.f);
    #pragma unroll
    for (int k = 0; k < 4; ++k) {
        const int j = k * NN + t;
        const int node = j >> 2, row = j & 3;
        o[j] = (row < 3) ? S[3 * node + row] : r3;
    }
}

extern "C" void kernel_launch(void* const* d_in, const int* in_sizes, int n_in,
                              void* d_out, int out_size) {
    const float* la  = (const float*)d_in[0];
    const float* tip = (const float*)d_in[1];
    float* out = (float*)d_out;

    const int B = in_sizes[0] / (3 * EE);

    pack_kernel<<<4, 256>>>(tip);

    // PDL: fk's grid may begin launching while pack is still running; the
    // entry-point grid-dependency sync orders the g_tip reads.
    cudaLaunchConfig_t cfg = {};
    cfg.gridDim = dim3((unsigned)B);
    cfg.blockDim = dim3(NN);
    cfg.dynamicSmemBytes = 0;
    cfg.stream = 0;
    cudaLaunchAttribute attr[1];
    attr[0].id = cudaLaunchAttributeProgrammaticStreamSerialization;
    attr[0].val.programmaticStreamSerializationAllowed = 1;
    cfg.attrs = attr;
    cfg.numAttrs = 1;
    cudaLaunchKernelEx(&cfg, fk_kernel, la, out);
}